// round 14
// baseline (speedup 1.0000x reference)
#include <cuda_runtime.h>
#include <cuda_fp16.h>
#include <cstdint>

#define NROWS 262144
#define DD 128
#define FEAT 64
#define TILE_M 128
#define NTILES_GRID (NROWS / TILE_M)   // 2048
#define CHUNK_A 8704                   // kernelA per-warp smem chunk (bytes)
#define SMEM_ALLOC_A 78336             // padded: 3x > 228KB -> max 2 CTAs/SM
#define CHUNK_B 4352                   // kernelB per-warp chunk (hi plane only)
#define SMEM_ALLOC_B 34816             // 8 * CHUNK_B; 3 CTAs/SM fits

typedef unsigned long long u64t;

// ---------------------------------------------------------------------------
// Device scratch
// ---------------------------------------------------------------------------
__device__ float  g_x0[(size_t)NROWS * DD];
__device__ float  g_x1[(size_t)NROWS * DD];
__device__ __half g_x0h[(size_t)NROWS * DD];   // fp16 mirror for gathers
__device__ __half g_x1h[(size_t)NROWS * DD];

// Weights pre-packed into mma.sync B-fragment lane order, fp16 hi/lo planes.
__device__ ulonglong2 g_W1h[4 * 8 * 32];   // K=64  (normalization folded in)
__device__ ulonglong2 g_W1l[4 * 8 * 32];
__device__ ulonglong2 g_W2h[8 * 8 * 32];   // K=128
__device__ ulonglong2 g_W2l[8 * 8 * 32];
__device__ ulonglong2 g_Wnh[8 * 8 * 32];
__device__ float g_b1f[DD];                // normalization-folded bias

__device__ __forceinline__ float lk(float x) { return x >= 0.f ? x : 0.01f * x; }

__device__ __forceinline__ uint32_t f2h2(float a, float b) {
    __half2 h = __floats2half2_rn(a, b);
    return *reinterpret_cast<uint32_t*>(&h);
}
__device__ __forceinline__ float2 h22f2(uint32_t u) {
    __half2 h = *reinterpret_cast<__half2*>(&u);
    return __half22float2(h);
}
__device__ __forceinline__ uint32_t havg2(uint32_t a, uint32_t b) {
    __half2 ha = *reinterpret_cast<__half2*>(&a);
    __half2 hb = *reinterpret_cast<__half2*>(&b);
    __half2 r = __hmul2(__hadd2(ha, hb), __floats2half2_rn(0.5f, 0.5f));
    return *reinterpret_cast<uint32_t*>(&r);
}
__device__ __forceinline__ float hiof(float w) {
    return __half2float(__float2half_rn(w));
}
__device__ __forceinline__ u64t pku(uint32_t lo, uint32_t hi) {
    return (u64t)lo | ((u64t)hi << 32);
}
__device__ __forceinline__ uint32_t smem_u32(const void* p) {
    uint32_t a;
    asm("{ .reg .u64 t; cvta.to.shared.u64 t, %1; cvt.u32.u64 %0, t; }" : "=r"(a) : "l"(p));
    return a;
}
__device__ __forceinline__ void ldm4(uint32_t a[4], uint32_t addr) {
    asm volatile("ldmatrix.sync.aligned.m8n8.x4.shared.b16 {%0,%1,%2,%3}, [%4];"
                 : "=r"(a[0]), "=r"(a[1]), "=r"(a[2]), "=r"(a[3]) : "r"(addr));
}
__device__ __forceinline__ void mma16816(float c[4], const uint32_t a[4],
                                         uint32_t b0, uint32_t b1) {
    asm volatile(
        "mma.sync.aligned.m16n8k16.row.col.f32.f16.f16.f32 "
        "{%0,%1,%2,%3},{%4,%5,%6,%7},{%8,%9},{%0,%1,%2,%3};"
        : "+f"(c[0]), "+f"(c[1]), "+f"(c[2]), "+f"(c[3])
        : "r"(a[0]), "r"(a[1]), "r"(a[2]), "r"(a[3]), "r"(b0), "r"(b1));
}

// ---------------------------------------------------------------------------
// Prep: pack weights into B-fragment planes; fold normalization into W1/b1.
// block 0 = W1 hi+lo (+b1f), block 1 = W2 hi+lo, block 2 = Wn hi only.
// ---------------------------------------------------------------------------
__global__ void prep(const float* __restrict__ smean, const float* __restrict__ sstd,
                     const float* __restrict__ W1, const float* __restrict__ b1,
                     const float* __restrict__ W2, const float* __restrict__ Wn)
{
    const int tid = threadIdx.x;
    const int bid = blockIdx.x;
    const float* W = (bid == 0) ? W1 : (bid == 1) ? W2 : Wn;
    ulonglong2* dh = (bid == 0) ? g_W1h : (bid == 1) ? g_W2h : g_Wnh;
    ulonglong2* dl = (bid == 0) ? g_W1l : (bid == 1) ? g_W2l : nullptr;
    const int nent = (bid == 0) ? 1024 : 2048;

    if (bid == 0) {
        for (int n = tid; n < DD; n += 256) {
            float acc = b1[n];
            for (int k = 0; k < FEAT; k++)
                acc -= smean[k] * (W1[k * DD + n] / (sstd[k] + 0.001f));
            g_b1f[n] = acc;
        }
    }
    for (int e = tid; e < nent; e += 256) {
        int ks = e >> 8, tp = (e >> 5) & 7, l = e & 31;
        u64t H[2], L[2];
        #pragma unroll
        for (int j = 0; j < 2; j++) {
            int n  = (2 * tp + j) * 8 + (l >> 2);
            int k0 = ks * 16 + (l & 3) * 2;
            float w00 = W[(k0    ) * DD + n], w01 = W[(k0 + 1) * DD + n];
            float w08 = W[(k0 + 8) * DD + n], w09 = W[(k0 + 9) * DD + n];
            if (bid == 0) {
                w00 /= (sstd[k0    ] + 0.001f); w01 /= (sstd[k0 + 1] + 0.001f);
                w08 /= (sstd[k0 + 8] + 0.001f); w09 /= (sstd[k0 + 9] + 0.001f);
            }
            H[j] = pku(f2h2(w00, w01), f2h2(w08, w09));
            L[j] = pku(f2h2(w00 - hiof(w00), w01 - hiof(w01)),
                       f2h2(w08 - hiof(w08), w09 - hiof(w09)));
        }
        dh[e] = make_ulonglong2(H[0], H[1]);
        if (dl) dl[e] = make_ulonglong2(L[0], L[1]);
    }
}

// ---------------------------------------------------------------------------
// 3-term split HMMA GEMM (accuracy-critical path; kernelA).
// ---------------------------------------------------------------------------
template<int KS>
__device__ __forceinline__ void hgemm_full(float c[16][4], uint32_t aAh, uint32_t aAl,
                                           const ulonglong2* __restrict__ gWh,
                                           const ulonglong2* __restrict__ gWl, int lane)
{
    #pragma unroll
    for (int ks = 0; ks < KS; ks++) {
        uint32_t ah[4], al[4];
        ldm4(ah, aAh + ks * 32);
        ldm4(al, aAl + ks * 32);
        #pragma unroll
        for (int tp = 0; tp < 8; tp++) {
            ulonglong2 wh = __ldg(gWh + (ks * 8 + tp) * 32 + lane);
            ulonglong2 wl = __ldg(gWl + (ks * 8 + tp) * 32 + lane);
            uint32_t h0 = (uint32_t)wh.x, h1 = (uint32_t)(wh.x >> 32);
            uint32_t l0 = (uint32_t)wl.x, l1 = (uint32_t)(wl.x >> 32);
            mma16816(c[2 * tp], ah, h0, h1);
            mma16816(c[2 * tp], ah, l0, l1);
            mma16816(c[2 * tp], al, h0, h1);
            h0 = (uint32_t)wh.y; h1 = (uint32_t)(wh.y >> 32);
            l0 = (uint32_t)wl.y; l1 = (uint32_t)(wl.y >> 32);
            mma16816(c[2 * tp + 1], ah, h0, h1);
            mma16816(c[2 * tp + 1], ah, l0, l1);
            mma16816(c[2 * tp + 1], al, h0, h1);
        }
    }
}

// 1-term fp16 half-width GEMM (kernelB: result damped x0.025 by rezero).
template<int KS>
__device__ __forceinline__ void hgemm_1t_half(float c[8][4], uint32_t aAh,
                                              const ulonglong2* __restrict__ gWh,
                                              int half, int lane)
{
    #pragma unroll
    for (int ks = 0; ks < KS; ks++) {
        uint32_t ah[4];
        ldm4(ah, aAh + ks * 32);
        #pragma unroll
        for (int tp = 0; tp < 4; tp++) {
            ulonglong2 wh = __ldg(gWh + (ks * 8 + half * 4 + tp) * 32 + lane);
            mma16816(c[2 * tp],     ah, (uint32_t)wh.x, (uint32_t)(wh.x >> 32));
            mma16816(c[2 * tp + 1], ah, (uint32_t)wh.y, (uint32_t)(wh.y >> 32));
        }
    }
}

// ---------------------------------------------------------------------------
// Kernel A: warp-independent; per-warp smem chunk with phase union:
//   phase1: A hi [0,2304) + A lo [2304,4608)   (pitch 72, 16 local rows)
//   phase2: H hi [0,4352) + H lo [4352,8704)   (pitch 136) — overwrites A,
//           safe per-warp (ldmatrix is warp-synchronous; chunk is warp-private).
// Also writes fp16 mirror g_x0h for kernelB gathers.
// ---------------------------------------------------------------------------
__global__ __launch_bounds__(256, 2)
void kernelA(const float* __restrict__ raw, const float* __restrict__ b2)
{
    extern __shared__ char smem[];
    const uint32_t sbase = smem_u32(smem);
    const int tid = threadIdx.x, warp = tid >> 5, lane = tid & 31;
    const int wrow = warp * 16, lane4 = lane & 3, lqr = lane >> 2;
    const int rowbase = blockIdx.x * TILE_M;
    const int CH = warp * CHUNK_A;

    // stage own 16 raw rows as fp16 hi/lo planes (local rows, pitch 72)
    #pragma unroll 4
    for (int i = 0; i < 16; i++) {
        float2 v = __ldg(reinterpret_cast<const float2*>(
                         raw + (size_t)(rowbase + wrow + i) * FEAT) + lane);
        uint32_t hu = f2h2(v.x, v.y);
        float2 hr = h22f2(hu);
        uint32_t lu = f2h2(v.x - hr.x, v.y - hr.y);
        *reinterpret_cast<uint32_t*>(smem + CH + (i * 72 + 2 * lane) * 2) = hu;
        *reinterpret_cast<uint32_t*>(smem + CH + 2304 + (i * 72 + 2 * lane) * 2) = lu;
    }
    __syncwarp();

    float c[16][4];
    // ---- GEMM1: h = leaky(x @ W1' + b1') ----
    #pragma unroll
    for (int nt = 0; nt < 16; nt++) {
        float2 b = __ldg(reinterpret_cast<const float2*>(g_b1f + nt * 8 + 2 * lane4));
        c[nt][0] = b.x; c[nt][1] = b.y; c[nt][2] = b.x; c[nt][3] = b.y;
    }
    {
        uint32_t aAh = sbase + CH + ((lane & 15) * 72 + (lane >> 4) * 8) * 2;
        hgemm_full<4>(c, aAh, aAh + 2304, g_W1h, g_W1l, lane);
    }
    __syncwarp();

    // h -> fp16 hi/lo planes (local rows lqr, lqr+8; pitch 136) over the A region
    #pragma unroll
    for (int nt = 0; nt < 16; nt++) {
        int col0 = nt * 8 + 2 * lane4;
        float h0 = lk(c[nt][0]), h1 = lk(c[nt][1]);
        float h2v = lk(c[nt][2]), h3 = lk(c[nt][3]);
        uint32_t hu = f2h2(h0, h1); float2 hr = h22f2(hu);
        *reinterpret_cast<uint32_t*>(smem + CH + (lqr * 136 + col0) * 2) = hu;
        *reinterpret_cast<uint32_t*>(smem + CH + 4352 + (lqr * 136 + col0) * 2) =
            f2h2(h0 - hr.x, h1 - hr.y);
        hu = f2h2(h2v, h3); hr = h22f2(hu);
        *reinterpret_cast<uint32_t*>(smem + CH + ((lqr + 8) * 136 + col0) * 2) = hu;
        *reinterpret_cast<uint32_t*>(smem + CH + 4352 + ((lqr + 8) * 136 + col0) * 2) =
            f2h2(h2v - hr.x, h3 - hr.y);
    }
    __syncwarp();

    // ---- GEMM2: y = leaky(leaky(h @ W2 + b2)) + h ----
    #pragma unroll
    for (int nt = 0; nt < 16; nt++) {
        float2 b = __ldg(reinterpret_cast<const float2*>(b2 + nt * 8 + 2 * lane4));
        c[nt][0] = b.x; c[nt][1] = b.y; c[nt][2] = b.x; c[nt][3] = b.y;
    }
    {
        uint32_t aHh = sbase + CH + ((lane & 15) * 136 + (lane >> 4) * 8) * 2;
        hgemm_full<8>(c, aHh, aHh + 4352, g_W2h, g_W2l, lane);
    }

    // ---- epilogue: residual + layernorm * 0.5 (+ fp16 mirror) ----
    float sA = 0.f, qA = 0.f, sB = 0.f, qB = 0.f;
    #pragma unroll
    for (int nt = 0; nt < 16; nt++) {
        int col0 = nt * 8 + 2 * lane4;
        float2 hA = h22f2(*reinterpret_cast<uint32_t*>(smem + CH + (lqr * 136 + col0) * 2));
        float2 lA = h22f2(*reinterpret_cast<uint32_t*>(smem + CH + 4352 + (lqr * 136 + col0) * 2));
        float2 hB = h22f2(*reinterpret_cast<uint32_t*>(smem + CH + ((lqr + 8) * 136 + col0) * 2));
        float2 lB = h22f2(*reinterpret_cast<uint32_t*>(smem + CH + 4352 + ((lqr + 8) * 136 + col0) * 2));
        float y0 = lk(lk(c[nt][0])) + (hA.x + lA.x);
        float y1 = lk(lk(c[nt][1])) + (hA.y + lA.y);
        float y2 = lk(lk(c[nt][2])) + (hB.x + lB.x);
        float y3 = lk(lk(c[nt][3])) + (hB.y + lB.y);
        c[nt][0] = y0; c[nt][1] = y1; c[nt][2] = y2; c[nt][3] = y3;
        sA += y0 + y1; qA += y0 * y0 + y1 * y1;
        sB += y2 + y3; qB += y2 * y2 + y3 * y3;
    }
    #pragma unroll
    for (int off = 1; off <= 2; off <<= 1) {
        sA += __shfl_xor_sync(0xffffffffu, sA, off);
        qA += __shfl_xor_sync(0xffffffffu, qA, off);
        sB += __shfl_xor_sync(0xffffffffu, sB, off);
        qB += __shfl_xor_sync(0xffffffffu, qB, off);
    }
    const float invD = 1.f / DD;
    float muA = sA * invD, muB = sB * invD;
    float scA = rsqrtf(qA * invD - muA * muA + 1e-5f) * 0.5f;
    float scB = rsqrtf(qB * invD - muB * muB + 1e-5f) * 0.5f;
    const size_t rowA = (size_t)(rowbase + wrow + lqr);
    const size_t rowB = rowA + 8;
    float* dA = g_x0 + rowA * DD;
    float* dB = g_x0 + rowB * DD;
    #pragma unroll
    for (int nt = 0; nt < 16; nt++) {
        int col0 = nt * 8 + 2 * lane4;
        float o0 = (c[nt][0] - muA) * scA, o1 = (c[nt][1] - muA) * scA;
        float o2 = (c[nt][2] - muB) * scB, o3 = (c[nt][3] - muB) * scB;
        *reinterpret_cast<float2*>(dA + col0) = make_float2(o0, o1);
        *reinterpret_cast<float2*>(dB + col0) = make_float2(o2, o3);
        *reinterpret_cast<uint32_t*>(g_x0h + rowA * DD + col0) = f2h2(o0, o1);
        *reinterpret_cast<uint32_t*>(g_x0h + rowB * DD + col0) = f2h2(o2, o3);
    }
}

// ---------------------------------------------------------------------------
// Kernel B: warp-independent, 1-term fp16 GEMM, column-halved accumulators
// (~80 regs -> 3 CTAs/SM). Gathers from fp16 mirror; per-warp chunk = hi plane.
// PHASE 0: writes g_x1 + g_x1h.  PHASE 1: writes d_out (+ w/v GEMVs).
// ---------------------------------------------------------------------------
template<int PHASE>
__global__ __launch_bounds__(256, 3)
void kernelB(const int* __restrict__ idmap,
             const float* __restrict__ bn, const float* __restrict__ rez,
             const float* __restrict__ Ww, const float* __restrict__ Wv,
             float* __restrict__ outx, float* __restrict__ outw, float* __restrict__ outv)
{
    extern __shared__ char smem[];
    const uint32_t sbase = smem_u32(smem);
    const int tid = threadIdx.x, warp = tid >> 5, lane = tid & 31;
    const int wrow = warp * 16, lane4 = lane & 3, lqr = lane >> 2;
    const int rowbase = blockIdx.x * TILE_M;
    const int CH = warp * CHUNK_B;
    const float*  __restrict__ xin  = (PHASE == 0) ? g_x0  : g_x1;
    const __half* __restrict__ xinh = (PHASE == 0) ? g_x0h : g_x1h;

    // gather-mean from fp16 mirror -> fp16 plane (local rows, pitch 136)
    #pragma unroll 4
    for (int i = 0; i < 16; i++) {
        int2 pr = __ldg(reinterpret_cast<const int2*>(idmap) + (rowbase + wrow + i));
        uint2 a = __ldg(reinterpret_cast<const uint2*>(xinh + (size_t)pr.x * DD) + lane);
        uint2 b = __ldg(reinterpret_cast<const uint2*>(xinh + (size_t)pr.y * DD) + lane);
        *reinterpret_cast<uint2*>(smem + CH + (i * 136 + 4 * lane) * 2) =
            make_uint2(havg2(a.x, b.x), havg2(a.y, b.y));
    }
    __syncwarp();

    const float scale = 0.25f * __ldg(rez);
    const size_t rA = (size_t)(rowbase + wrow + lqr), rB = rA + 8;
    float* dst = (PHASE == 0) ? g_x1 : outx;
    const uint32_t aGh = sbase + CH + ((lane & 15) * 136 + (lane >> 4) * 8) * 2;
    float pwA = 0.f, pvA = 0.f, pwB = 0.f, pvB = 0.f;

    #pragma unroll
    for (int half = 0; half < 2; half++) {
        float c[8][4];
        #pragma unroll
        for (int ntl = 0; ntl < 8; ntl++) {
            float2 b = __ldg(reinterpret_cast<const float2*>(bn + (half * 8 + ntl) * 8 + 2 * lane4));
            c[ntl][0] = b.x; c[ntl][1] = b.y; c[ntl][2] = b.x; c[ntl][3] = b.y;
        }
        hgemm_1t_half<8>(c, aGh, g_Wnh, half, lane);

        #pragma unroll
        for (int ntl = 0; ntl < 8; ntl++) {
            int col0 = (half * 8 + ntl) * 8 + 2 * lane4;
            float2 xA = __ldg(reinterpret_cast<const float2*>(xin + rA * DD + col0));
            float2 xB = __ldg(reinterpret_cast<const float2*>(xin + rB * DD + col0));
            float o0 = xA.x + lk(c[ntl][0]) * scale;
            float o1 = xA.y + lk(c[ntl][1]) * scale;
            float o2 = xB.x + lk(c[ntl][2]) * scale;
            float o3 = xB.y + lk(c[ntl][3]) * scale;
            *reinterpret_cast<float2*>(dst + rA * DD + col0) = make_float2(o0, o1);
            *reinterpret_cast<float2*>(dst + rB * DD + col0) = make_float2(o2, o3);
            if (PHASE == 0) {
                *reinterpret_cast<uint32_t*>(g_x1h + rA * DD + col0) = f2h2(o0, o1);
                *reinterpret_cast<uint32_t*>(g_x1h + rB * DD + col0) = f2h2(o2, o3);
            } else {
                float2 w2 = __ldg(reinterpret_cast<const float2*>(Ww + col0));
                float2 v2 = __ldg(reinterpret_cast<const float2*>(Wv + col0));
                pwA += o0 * w2.x + o1 * w2.y;  pvA += o0 * v2.x + o1 * v2.y;
                pwB += o2 * w2.x + o3 * w2.y;  pvB += o2 * v2.x + o3 * v2.y;
            }
        }
    }
    if (PHASE == 1) {
        #pragma unroll
        for (int off = 1; off <= 2; off <<= 1) {
            pwA += __shfl_xor_sync(0xffffffffu, pwA, off);
            pvA += __shfl_xor_sync(0xffffffffu, pvA, off);
            pwB += __shfl_xor_sync(0xffffffffu, pwB, off);
            pvB += __shfl_xor_sync(0xffffffffu, pvB, off);
        }
        if (lane4 == 0) {
            outw[rA] = pwA; outv[rA] = pvA;
            outw[rB] = pwB; outv[rB] = pvB;
        }
    }
}

// ---------------------------------------------------------------------------
extern "C" void kernel_launch(void* const* d_in, const int* in_sizes, int n_in,
                              void* d_out, int out_size)
{
    const float* raw   = (const float*)d_in[0];
    // d_in[1] = uids (unused)
    const int*   idmap = (const int*)  d_in[2];
    const float* smean = (const float*)d_in[3];
    const float* sstd  = (const float*)d_in[4];
    const float* W1    = (const float*)d_in[5];
    const float* b1    = (const float*)d_in[6];
    const float* W2    = (const float*)d_in[7];
    const float* b2    = (const float*)d_in[8];
    const float* Wn    = (const float*)d_in[9];
    const float* bn    = (const float*)d_in[10];
    const float* rez   = (const float*)d_in[11];
    const float* Ww    = (const float*)d_in[12];
    const float* Wv    = (const float*)d_in[13];
    float* out = (float*)d_out;

    cudaFuncSetAttribute(kernelA,    cudaFuncAttributeMaxDynamicSharedMemorySize, SMEM_ALLOC_A);
    cudaFuncSetAttribute(kernelB<0>, cudaFuncAttributeMaxDynamicSharedMemorySize, SMEM_ALLOC_B);
    cudaFuncSetAttribute(kernelB<1>, cudaFuncAttributeMaxDynamicSharedMemorySize, SMEM_ALLOC_B);

    prep<<<3, 256>>>(smean, sstd, W1, b1, W2, Wn);
    kernelA<<<NTILES_GRID, 256, SMEM_ALLOC_A>>>(raw, b2);
    kernelB<0><<<NTILES_GRID, 256, SMEM_ALLOC_B>>>(idmap, bn, rez, Ww, Wv,
                                                   nullptr, nullptr, nullptr);
    kernelB<1><<<NTILES_GRID, 256, SMEM_ALLOC_B>>>(idmap, bn, rez, Ww, Wv,
                                                   out,
                                                   out + (size_t)NROWS * DD,
                                                   out + (size_t)NROWS * DD + NROWS);
}

// round 16
// speedup vs baseline: 1.2701x; 1.2701x over previous
#include <cuda_runtime.h>
#include <cuda_fp16.h>
#include <cstdint>

#define NROWS 262144
#define DD 128
#define FEAT 64
#define TILE_M 128
#define NTILES_GRID (NROWS / TILE_M)   // 2048
#define CHUNK_A 12544                  // per-warp: H hi plane 4352 + h fp32 8192
#define SMEM_ALLOC_A 100352            // 8*CHUNK_A; 2 CTAs/SM (3x > 228KB)
#define CHUNK_B 8704                   // R13 layout (hi plane used, padded)
#define SMEM_ALLOC_B 78336             // 2 CTAs/SM

typedef unsigned long long u64t;

// ---------------------------------------------------------------------------
// Device scratch
// ---------------------------------------------------------------------------
__device__ float g_x0[(size_t)NROWS * DD];
__device__ float g_x1[(size_t)NROWS * DD];

// Weights pre-packed into mma.sync B-fragment lane order, fp16 hi/lo planes.
__device__ ulonglong2 g_W1h[4 * 8 * 32];   // K=64  (normalization folded in)
__device__ ulonglong2 g_W1l[4 * 8 * 32];
__device__ ulonglong2 g_W2h[8 * 8 * 32];   // K=128
__device__ ulonglong2 g_W2l[8 * 8 * 32];
__device__ ulonglong2 g_Wnh[8 * 8 * 32];
__device__ float g_b1f[DD];                // normalization-folded bias

__device__ __forceinline__ float lk(float x) { return x >= 0.f ? x : 0.01f * x; }

__device__ __forceinline__ uint32_t f2h2(float a, float b) {
    __half2 h = __floats2half2_rn(a, b);
    return *reinterpret_cast<uint32_t*>(&h);
}
__device__ __forceinline__ float2 h22f2(uint32_t u) {
    __half2 h = *reinterpret_cast<__half2*>(&u);
    return __half22float2(h);
}
__device__ __forceinline__ float hiof(float w) {
    return __half2float(__float2half_rn(w));
}
__device__ __forceinline__ u64t pku(uint32_t lo, uint32_t hi) {
    return (u64t)lo | ((u64t)hi << 32);
}
__device__ __forceinline__ uint32_t smem_u32(const void* p) {
    uint32_t a;
    asm("{ .reg .u64 t; cvta.to.shared.u64 t, %1; cvt.u32.u64 %0, t; }" : "=r"(a) : "l"(p));
    return a;
}
__device__ __forceinline__ void ldm4(uint32_t a[4], uint32_t addr) {
    asm volatile("ldmatrix.sync.aligned.m8n8.x4.shared.b16 {%0,%1,%2,%3}, [%4];"
                 : "=r"(a[0]), "=r"(a[1]), "=r"(a[2]), "=r"(a[3]) : "r"(addr));
}
__device__ __forceinline__ void mma16816(float c[4], const uint32_t a[4],
                                         uint32_t b0, uint32_t b1) {
    asm volatile(
        "mma.sync.aligned.m16n8k16.row.col.f32.f16.f16.f32 "
        "{%0,%1,%2,%3},{%4,%5,%6,%7},{%8,%9},{%0,%1,%2,%3};"
        : "+f"(c[0]), "+f"(c[1]), "+f"(c[2]), "+f"(c[3])
        : "r"(a[0]), "r"(a[1]), "r"(a[2]), "r"(a[3]), "r"(b0), "r"(b1));
}

// ---------------------------------------------------------------------------
// Prep: pack weights into B-fragment planes; fold normalization into W1/b1.
// block 0 = W1 hi+lo (+b1f), block 1 = W2 hi+lo, block 2 = Wn hi only.
// ---------------------------------------------------------------------------
__global__ void prep(const float* __restrict__ smean, const float* __restrict__ sstd,
                     const float* __restrict__ W1, const float* __restrict__ b1,
                     const float* __restrict__ W2, const float* __restrict__ Wn)
{
    const int tid = threadIdx.x;
    const int bid = blockIdx.x;
    const float* W = (bid == 0) ? W1 : (bid == 1) ? W2 : Wn;
    ulonglong2* dh = (bid == 0) ? g_W1h : (bid == 1) ? g_W2h : g_Wnh;
    ulonglong2* dl = (bid == 0) ? g_W1l : (bid == 1) ? g_W2l : nullptr;
    const int nent = (bid == 0) ? 1024 : 2048;

    if (bid == 0) {
        for (int n = tid; n < DD; n += 256) {
            float acc = b1[n];
            for (int k = 0; k < FEAT; k++)
                acc -= smean[k] * (W1[k * DD + n] / (sstd[k] + 0.001f));
            g_b1f[n] = acc;
        }
    }
    for (int e = tid; e < nent; e += 256) {
        int ks = e >> 8, tp = (e >> 5) & 7, l = e & 31;
        u64t H[2], L[2];
        #pragma unroll
        for (int j = 0; j < 2; j++) {
            int n  = (2 * tp + j) * 8 + (l >> 2);
            int k0 = ks * 16 + (l & 3) * 2;
            float w00 = W[(k0    ) * DD + n], w01 = W[(k0 + 1) * DD + n];
            float w08 = W[(k0 + 8) * DD + n], w09 = W[(k0 + 9) * DD + n];
            if (bid == 0) {
                w00 /= (sstd[k0    ] + 0.001f); w01 /= (sstd[k0 + 1] + 0.001f);
                w08 /= (sstd[k0 + 8] + 0.001f); w09 /= (sstd[k0 + 9] + 0.001f);
            }
            H[j] = pku(f2h2(w00, w01), f2h2(w08, w09));
            L[j] = pku(f2h2(w00 - hiof(w00), w01 - hiof(w01)),
                       f2h2(w08 - hiof(w08), w09 - hiof(w09)));
        }
        dh[e] = make_ulonglong2(H[0], H[1]);
        if (dl) dl[e] = make_ulonglong2(L[0], L[1]);
    }
}

// ---------------------------------------------------------------------------
// 2-term split HMMA GEMM (kernelA): ah*Wh + ah*Wl  (weight-rounding corrected;
// activation-lo term dropped — ~6e-5 relative, threshold is 1e-3).
// ---------------------------------------------------------------------------
template<int KS>
__device__ __forceinline__ void hgemm_2t(float c[16][4], uint32_t aAh,
                                         const ulonglong2* __restrict__ gWh,
                                         const ulonglong2* __restrict__ gWl, int lane)
{
    #pragma unroll
    for (int ks = 0; ks < KS; ks++) {
        uint32_t ah[4];
        ldm4(ah, aAh + ks * 32);
        #pragma unroll
        for (int tp = 0; tp < 8; tp++) {
            ulonglong2 wh = __ldg(gWh + (ks * 8 + tp) * 32 + lane);
            ulonglong2 wl = __ldg(gWl + (ks * 8 + tp) * 32 + lane);
            mma16816(c[2 * tp],     ah, (uint32_t)wh.x, (uint32_t)(wh.x >> 32));
            mma16816(c[2 * tp],     ah, (uint32_t)wl.x, (uint32_t)(wl.x >> 32));
            mma16816(c[2 * tp + 1], ah, (uint32_t)wh.y, (uint32_t)(wh.y >> 32));
            mma16816(c[2 * tp + 1], ah, (uint32_t)wl.y, (uint32_t)(wl.y >> 32));
        }
    }
}

// 1-term fp16 GEMM (kernelB: result damped x0.025 by rezero -> fp16 suffices).
template<int KS>
__device__ __forceinline__ void hgemm_1t(float c[16][4], uint32_t aAh,
                                         const ulonglong2* __restrict__ gWh, int lane)
{
    #pragma unroll
    for (int ks = 0; ks < KS; ks++) {
        uint32_t ah[4];
        ldm4(ah, aAh + ks * 32);
        #pragma unroll
        for (int tp = 0; tp < 8; tp++) {
            ulonglong2 wh = __ldg(gWh + (ks * 8 + tp) * 32 + lane);
            mma16816(c[2 * tp],     ah, (uint32_t)wh.x, (uint32_t)(wh.x >> 32));
            mma16816(c[2 * tp + 1], ah, (uint32_t)wh.y, (uint32_t)(wh.y >> 32));
        }
    }
}

// ---------------------------------------------------------------------------
// Kernel A: warp-independent; per-warp smem chunk, phase union:
//   phase1: A hi plane [0,2304)                 (pitch 72, 16 local rows)
//   phase2: H hi plane [0,4352) (pitch 136)  +  h fp32 [4352,12544)
//           in thread-private float4 slots (nt*32+lane)*16 — conflict-free.
// ---------------------------------------------------------------------------
__global__ __launch_bounds__(256, 2)
void kernelA(const float* __restrict__ raw, const float* __restrict__ b2)
{
    extern __shared__ char smem[];
    const uint32_t sbase = smem_u32(smem);
    const int tid = threadIdx.x, warp = tid >> 5, lane = tid & 31;
    const int wrow = warp * 16, lane4 = lane & 3, lqr = lane >> 2;
    const int rowbase = blockIdx.x * TILE_M;
    const int CH = warp * CHUNK_A;

    // stage own 16 raw rows as fp16 hi plane (local rows, pitch 72)
    #pragma unroll 4
    for (int i = 0; i < 16; i++) {
        float2 v = __ldg(reinterpret_cast<const float2*>(
                         raw + (size_t)(rowbase + wrow + i) * FEAT) + lane);
        *reinterpret_cast<uint32_t*>(smem + CH + (i * 72 + 2 * lane) * 2) = f2h2(v.x, v.y);
    }
    __syncwarp();

    float c[16][4];
    // ---- GEMM1: h = leaky(x @ W1' + b1')  (2-term) ----
    #pragma unroll
    for (int nt = 0; nt < 16; nt++) {
        float2 b = __ldg(reinterpret_cast<const float2*>(g_b1f + nt * 8 + 2 * lane4));
        c[nt][0] = b.x; c[nt][1] = b.y; c[nt][2] = b.x; c[nt][3] = b.y;
    }
    {
        uint32_t aAh = sbase + CH + ((lane & 15) * 72 + (lane >> 4) * 8) * 2;
        hgemm_2t<4>(c, aAh, g_W1h, g_W1l, lane);
    }
    __syncwarp();

    // h -> fp16 hi plane (pitch 136) + exact fp32 in private slots
    #pragma unroll
    for (int nt = 0; nt < 16; nt++) {
        int col0 = nt * 8 + 2 * lane4;
        float h0 = lk(c[nt][0]), h1 = lk(c[nt][1]);
        float h2v = lk(c[nt][2]), h3 = lk(c[nt][3]);
        *reinterpret_cast<uint32_t*>(smem + CH + (lqr * 136 + col0) * 2)       = f2h2(h0, h1);
        *reinterpret_cast<uint32_t*>(smem + CH + ((lqr + 8) * 136 + col0) * 2) = f2h2(h2v, h3);
        *reinterpret_cast<float4*>(smem + CH + 4352 + (nt * 32 + lane) * 16) =
            make_float4(h0, h1, h2v, h3);
    }
    __syncwarp();

    // ---- GEMM2: y = leaky(leaky(h @ W2 + b2)) + h  (2-term) ----
    #pragma unroll
    for (int nt = 0; nt < 16; nt++) {
        float2 b = __ldg(reinterpret_cast<const float2*>(b2 + nt * 8 + 2 * lane4));
        c[nt][0] = b.x; c[nt][1] = b.y; c[nt][2] = b.x; c[nt][3] = b.y;
    }
    {
        uint32_t aHh = sbase + CH + ((lane & 15) * 136 + (lane >> 4) * 8) * 2;
        hgemm_2t<8>(c, aHh, g_W2h, g_W2l, lane);
    }

    // ---- epilogue: residual (exact fp32 h) + layernorm * 0.5 ----
    float sA = 0.f, qA = 0.f, sB = 0.f, qB = 0.f;
    #pragma unroll
    for (int nt = 0; nt < 16; nt++) {
        float4 h = *reinterpret_cast<float4*>(smem + CH + 4352 + (nt * 32 + lane) * 16);
        float y0 = lk(lk(c[nt][0])) + h.x;
        float y1 = lk(lk(c[nt][1])) + h.y;
        float y2 = lk(lk(c[nt][2])) + h.z;
        float y3 = lk(lk(c[nt][3])) + h.w;
        c[nt][0] = y0; c[nt][1] = y1; c[nt][2] = y2; c[nt][3] = y3;
        sA += y0 + y1; qA += y0 * y0 + y1 * y1;
        sB += y2 + y3; qB += y2 * y2 + y3 * y3;
    }
    #pragma unroll
    for (int off = 1; off <= 2; off <<= 1) {
        sA += __shfl_xor_sync(0xffffffffu, sA, off);
        qA += __shfl_xor_sync(0xffffffffu, qA, off);
        sB += __shfl_xor_sync(0xffffffffu, sB, off);
        qB += __shfl_xor_sync(0xffffffffu, qB, off);
    }
    const float invD = 1.f / DD;
    float muA = sA * invD, muB = sB * invD;
    float scA = rsqrtf(qA * invD - muA * muA + 1e-5f) * 0.5f;
    float scB = rsqrtf(qB * invD - muB * muB + 1e-5f) * 0.5f;
    float* dA = g_x0 + (size_t)(rowbase + wrow + lqr) * DD;
    float* dB = g_x0 + (size_t)(rowbase + wrow + lqr + 8) * DD;
    #pragma unroll
    for (int nt = 0; nt < 16; nt++) {
        int col0 = nt * 8 + 2 * lane4;
        *reinterpret_cast<float2*>(dA + col0) =
            make_float2((c[nt][0] - muA) * scA, (c[nt][1] - muA) * scA);
        *reinterpret_cast<float2*>(dB + col0) =
            make_float2((c[nt][2] - muB) * scB, (c[nt][3] - muB) * scB);
    }
}

// ---------------------------------------------------------------------------
// Kernel B (exact R13 form): warp-independent, 1-term fp16 GEMM, full-width
// accumulators, 2 CTAs/SM. Per-warp chunk holds G hi plane [0,4352).
// ---------------------------------------------------------------------------
template<int PHASE>
__global__ __launch_bounds__(256, 2)
void kernelB(const int* __restrict__ idmap,
             const float* __restrict__ bn, const float* __restrict__ rez,
             const float* __restrict__ Ww, const float* __restrict__ Wv,
             float* __restrict__ outx, float* __restrict__ outw, float* __restrict__ outv)
{
    extern __shared__ char smem[];
    const uint32_t sbase = smem_u32(smem);
    const int tid = threadIdx.x, warp = tid >> 5, lane = tid & 31;
    const int wrow = warp * 16, lane4 = lane & 3, lqr = lane >> 2;
    const int rowbase = blockIdx.x * TILE_M;
    const int CH = warp * CHUNK_B;
    const float* __restrict__ xin = (PHASE == 0) ? g_x0 : g_x1;

    // gather-mean -> single fp16 plane (local rows, pitch 136)
    #pragma unroll 4
    for (int i = 0; i < 16; i++) {
        int2 pr = __ldg(reinterpret_cast<const int2*>(idmap) + (rowbase + wrow + i));
        float4 a = __ldg(reinterpret_cast<const float4*>(xin + (size_t)pr.x * DD) + lane);
        float4 b = __ldg(reinterpret_cast<const float4*>(xin + (size_t)pr.y * DD) + lane);
        uint32_t h01 = f2h2(0.5f * (a.x + b.x), 0.5f * (a.y + b.y));
        uint32_t h23 = f2h2(0.5f * (a.z + b.z), 0.5f * (a.w + b.w));
        *reinterpret_cast<uint2*>(smem + CH + (i * 136 + 4 * lane) * 2) = make_uint2(h01, h23);
    }
    __syncwarp();

    float c[16][4];
    #pragma unroll
    for (int nt = 0; nt < 16; nt++) {
        float2 b = __ldg(reinterpret_cast<const float2*>(bn + nt * 8 + 2 * lane4));
        c[nt][0] = b.x; c[nt][1] = b.y; c[nt][2] = b.x; c[nt][3] = b.y;
    }
    {
        uint32_t aGh = sbase + CH + ((lane & 15) * 136 + (lane >> 4) * 8) * 2;
        hgemm_1t<8>(c, aGh, g_Wnh, lane);
    }

    // ---- epilogue: o = xin + leaky(acc) * scale (+ fused w/v GEMV in phase 1)
    const float scale = 0.25f * __ldg(rez);
    const size_t rA = (size_t)(rowbase + wrow + lqr), rB = rA + 8;
    float* dst = (PHASE == 0) ? g_x1 : outx;
    float pwA = 0.f, pvA = 0.f, pwB = 0.f, pvB = 0.f;
    #pragma unroll
    for (int nt = 0; nt < 16; nt++) {
        int col0 = nt * 8 + 2 * lane4;
        float2 xA = __ldg(reinterpret_cast<const float2*>(xin + rA * DD + col0));
        float2 xB = __ldg(reinterpret_cast<const float2*>(xin + rB * DD + col0));
        float o0 = xA.x + lk(c[nt][0]) * scale;
        float o1 = xA.y + lk(c[nt][1]) * scale;
        float o2 = xB.x + lk(c[nt][2]) * scale;
        float o3 = xB.y + lk(c[nt][3]) * scale;
        *reinterpret_cast<float2*>(dst + rA * DD + col0) = make_float2(o0, o1);
        *reinterpret_cast<float2*>(dst + rB * DD + col0) = make_float2(o2, o3);
        if (PHASE == 1) {
            float2 w2 = __ldg(reinterpret_cast<const float2*>(Ww + col0));
            float2 v2 = __ldg(reinterpret_cast<const float2*>(Wv + col0));
            pwA += o0 * w2.x + o1 * w2.y;  pvA += o0 * v2.x + o1 * v2.y;
            pwB += o2 * w2.x + o3 * w2.y;  pvB += o2 * v2.x + o3 * v2.y;
        }
    }
    if (PHASE == 1) {
        #pragma unroll
        for (int off = 1; off <= 2; off <<= 1) {
            pwA += __shfl_xor_sync(0xffffffffu, pwA, off);
            pvA += __shfl_xor_sync(0xffffffffu, pvA, off);
            pwB += __shfl_xor_sync(0xffffffffu, pwB, off);
            pvB += __shfl_xor_sync(0xffffffffu, pvB, off);
        }
        if (lane4 == 0) {
            outw[rA] = pwA; outv[rA] = pvA;
            outw[rB] = pwB; outv[rB] = pvB;
        }
    }
}

// ---------------------------------------------------------------------------
extern "C" void kernel_launch(void* const* d_in, const int* in_sizes, int n_in,
                              void* d_out, int out_size)
{
    const float* raw   = (const float*)d_in[0];
    // d_in[1] = uids (unused)
    const int*   idmap = (const int*)  d_in[2];
    const float* smean = (const float*)d_in[3];
    const float* sstd  = (const float*)d_in[4];
    const float* W1    = (const float*)d_in[5];
    const float* b1    = (const float*)d_in[6];
    const float* W2    = (const float*)d_in[7];
    const float* b2    = (const float*)d_in[8];
    const float* Wn    = (const float*)d_in[9];
    const float* bn    = (const float*)d_in[10];
    const float* rez   = (const float*)d_in[11];
    const float* Ww    = (const float*)d_in[12];
    const float* Wv    = (const float*)d_in[13];
    float* out = (float*)d_out;

    cudaFuncSetAttribute(kernelA,    cudaFuncAttributeMaxDynamicSharedMemorySize, SMEM_ALLOC_A);
    cudaFuncSetAttribute(kernelB<0>, cudaFuncAttributeMaxDynamicSharedMemorySize, SMEM_ALLOC_B);
    cudaFuncSetAttribute(kernelB<1>, cudaFuncAttributeMaxDynamicSharedMemorySize, SMEM_ALLOC_B);

    prep<<<3, 256>>>(smean, sstd, W1, b1, W2, Wn);
    kernelA<<<NTILES_GRID, 256, SMEM_ALLOC_A>>>(raw, b2);
    kernelB<0><<<NTILES_GRID, 256, SMEM_ALLOC_B>>>(idmap, bn, rez, Ww, Wv,
                                                   nullptr, nullptr, nullptr);
    kernelB<1><<<NTILES_GRID, 256, SMEM_ALLOC_B>>>(idmap, bn, rez, Ww, Wv,
                                                   out,
                                                   out + (size_t)NROWS * DD,
                                                   out + (size_t)NROWS * DD + NROWS);
}